// round 1
// baseline (speedup 1.0000x reference)
#include <cuda_runtime.h>
#include <math.h>

#define T_TOK   2048
#define HDIM    1024
#define NEXP    16
#define IDIM    512
#define TOPK    4
#define NASSIGN (T_TOK * TOPK)

// ---------------- scratch (static device globals; no allocation) ----------------
__device__ int   g_cnt[NEXP];
__device__ int   g_off[NEXP];
__device__ int   g_tokens[NEXP * T_TOK];        // token ids per expert
__device__ int   g_sel_e[NASSIGN];              // per (token, k): expert id
__device__ int   g_sel_slot[NASSIGN];           // per (token, k): slot within expert
__device__ float g_sel_w[NASSIGN];              // per (token, k): combine weight
__device__ float g_hidden[(NASSIGN + 64) * IDIM];  // silu(x@wg)*(x@wu), padded rows
__device__ float g_down[(NASSIGN + 64) * HDIM];    // hidden @ wd, per assignment

// ---------------- kernel 0: reset counters ----------------
__global__ void zero_kernel() {
    if (threadIdx.x < NEXP) g_cnt[threadIdx.x] = 0;
}

// ---------------- kernel 1: router (logits + top-4 + dispatch) ----------------
// 256 threads = 16 tokens x 16 experts per block
__global__ void router_kernel(const float* __restrict__ x,
                              const float* __restrict__ wgt,
                              float* __restrict__ logits_out,
                              int write_logits) {
    __shared__ float sl[16][17];
    int tl = threadIdx.x >> 4;   // local token 0..15
    int e  = threadIdx.x & 15;   // expert 0..15
    int t  = blockIdx.x * 16 + tl;

    const float* xr = x + (size_t)t * HDIM;
    float acc = 0.f;
    #pragma unroll 4
    for (int h = 0; h < HDIM; h += 4) {
        float4 xv = *(const float4*)(xr + h);
        acc += xv.x * wgt[(h + 0) * NEXP + e];
        acc += xv.y * wgt[(h + 1) * NEXP + e];
        acc += xv.z * wgt[(h + 2) * NEXP + e];
        acc += xv.w * wgt[(h + 3) * NEXP + e];
    }
    sl[tl][e] = acc;
    if (write_logits) logits_out[(size_t)t * NEXP + e] = acc;
    __syncthreads();

    if (e == 0) {
        float v[NEXP];
        #pragma unroll
        for (int i = 0; i < NEXP; i++) v[i] = sl[tl][i];

        int   sel[TOPK];
        float selv[TOPK];
        #pragma unroll
        for (int k = 0; k < TOPK; k++) {
            int bi = 0; float bv = -INFINITY;
            #pragma unroll
            for (int i = 0; i < NEXP; i++) {
                if (v[i] > bv) { bv = v[i]; bi = i; }
            }
            sel[k] = bi; selv[k] = bv; v[bi] = -INFINITY;
        }
        // norm_topk_prob: softmax denominator cancels -> exact over top-4
        float mx = selv[0];
        float ex[TOPK], s = 0.f;
        #pragma unroll
        for (int k = 0; k < TOPK; k++) { ex[k] = expf(selv[k] - mx); s += ex[k]; }
        float inv = 1.f / s;
        #pragma unroll
        for (int k = 0; k < TOPK; k++) {
            int ee   = sel[k];
            int slot = atomicAdd(&g_cnt[ee], 1);
            g_tokens[ee * T_TOK + slot] = t;
            g_sel_e[t * TOPK + k]    = ee;
            g_sel_slot[t * TOPK + k] = slot;
            g_sel_w[t * TOPK + k]    = ex[k] * inv;
        }
    }
}

// ---------------- kernel 2: exclusive scan of counts (16 elems) ----------------
__global__ void scan_kernel() {
    if (threadIdx.x == 0) {
        int o = 0;
        for (int e = 0; e < NEXP; e++) { g_off[e] = o; o += g_cnt[e]; }
    }
}

// ---------------- kernel 3: gate+up GEMM with fused SiLU*up epilogue ----------------
// grid: (IDIM/64=8, T/64=32, NEXP=16), block 256 threads, 64x64 tile, BK=16
__global__ __launch_bounds__(256) void moe_gemm1(
        const float* __restrict__ x,
        const float* __restrict__ wg_all,
        const float* __restrict__ wu_all) {
    int e   = blockIdx.z;
    int cnt = g_cnt[e];
    int m0  = blockIdx.y * 64;
    if (m0 >= cnt) return;
    int n0  = blockIdx.x * 64;

    const float* wg = wg_all + (size_t)e * HDIM * IDIM;
    const float* wu = wu_all + (size_t)e * HDIM * IDIM;

    __shared__ float As[16][68];   // [k][m], padded for float4-aligned reads
    __shared__ float Bg[16][64];
    __shared__ float Bu[16][64];
    __shared__ int   stok[64];

    int tid = threadIdx.x;
    if (tid < 64) {
        int m = m0 + tid;
        stok[tid] = (m < cnt) ? g_tokens[e * T_TOK + m] : g_tokens[e * T_TOK];
    }
    __syncthreads();

    int tr = tid >> 4, tc = tid & 15;          // compute mapping
    int ar = tid >> 2, ac = (tid & 3) * 4;     // A-load mapping
    int br = tid >> 4, bc = (tid & 15) * 4;    // B-load mapping
    size_t arow = (size_t)stok[ar] * HDIM;

    float accg[4][4] = {}, accu[4][4] = {};

    for (int k0 = 0; k0 < HDIM; k0 += 16) {
        float4 av  = *(const float4*)(x  + arow + k0 + ac);
        float4 bgv = *(const float4*)(wg + (size_t)(k0 + br) * IDIM + n0 + bc);
        float4 buv = *(const float4*)(wu + (size_t)(k0 + br) * IDIM + n0 + bc);
        __syncthreads();
        As[ac + 0][ar] = av.x; As[ac + 1][ar] = av.y;
        As[ac + 2][ar] = av.z; As[ac + 3][ar] = av.w;
        *(float4*)&Bg[br][bc] = bgv;
        *(float4*)&Bu[br][bc] = buv;
        __syncthreads();
        #pragma unroll
        for (int k = 0; k < 16; k++) {
            float4 a  = *(const float4*)&As[k][tr * 4];
            float4 bg = *(const float4*)&Bg[k][tc * 4];
            float4 bu = *(const float4*)&Bu[k][tc * 4];
            float aa[4] = {a.x, a.y, a.z, a.w};
            float gg[4] = {bg.x, bg.y, bg.z, bg.w};
            float uu[4] = {bu.x, bu.y, bu.z, bu.w};
            #pragma unroll
            for (int i = 0; i < 4; i++)
                #pragma unroll
                for (int j = 0; j < 4; j++) {
                    accg[i][j] += aa[i] * gg[j];
                    accu[i][j] += aa[i] * uu[j];
                }
        }
    }

    int base = g_off[e] + m0;
    #pragma unroll
    for (int i = 0; i < 4; i++) {
        int m = tr * 4 + i;
        if (m0 + m < cnt) {
            float hv[4];
            #pragma unroll
            for (int j = 0; j < 4; j++) {
                float g = accg[i][j];
                float u = accu[i][j];
                hv[j] = (g / (1.f + __expf(-g))) * u;   // silu(g) * u
            }
            *(float4*)(g_hidden + (size_t)(base + m) * IDIM + n0 + tc * 4)
                = make_float4(hv[0], hv[1], hv[2], hv[3]);
        }
    }
}

// ---------------- kernel 4: down GEMM (hidden @ wd) ----------------
// grid: (HDIM/64=16, T/64=32, NEXP=16), block 256, 64x64 tile, BK=16
__global__ __launch_bounds__(256) void moe_gemm2(const float* __restrict__ wd_all) {
    int e   = blockIdx.z;
    int cnt = g_cnt[e];
    int m0  = blockIdx.y * 64;
    if (m0 >= cnt) return;
    int n0  = blockIdx.x * 64;

    const float* wd = wd_all + (size_t)e * IDIM * HDIM;
    int base = g_off[e] + m0;

    __shared__ float As[16][68];
    __shared__ float Bs[16][64];

    int tid = threadIdx.x;
    int tr = tid >> 4, tc = tid & 15;
    int ar = tid >> 2, ac = (tid & 3) * 4;
    int br = tid >> 4, bc = (tid & 15) * 4;
    size_t arow = (size_t)(base + ar) * IDIM;

    float acc[4][4] = {};

    for (int k0 = 0; k0 < IDIM; k0 += 16) {
        float4 av = *(const float4*)(g_hidden + arow + k0 + ac);
        float4 bv = *(const float4*)(wd + (size_t)(k0 + br) * HDIM + n0 + bc);
        __syncthreads();
        As[ac + 0][ar] = av.x; As[ac + 1][ar] = av.y;
        As[ac + 2][ar] = av.z; As[ac + 3][ar] = av.w;
        *(float4*)&Bs[br][bc] = bv;
        __syncthreads();
        #pragma unroll
        for (int k = 0; k < 16; k++) {
            float4 a = *(const float4*)&As[k][tr * 4];
            float4 b = *(const float4*)&Bs[k][tc * 4];
            float aa[4] = {a.x, a.y, a.z, a.w};
            float bb[4] = {b.x, b.y, b.z, b.w};
            #pragma unroll
            for (int i = 0; i < 4; i++)
                #pragma unroll
                for (int j = 0; j < 4; j++)
                    acc[i][j] += aa[i] * bb[j];
        }
    }

    #pragma unroll
    for (int i = 0; i < 4; i++) {
        int m = tr * 4 + i;
        if (m0 + m < cnt) {
            *(float4*)(g_down + (size_t)(base + m) * HDIM + n0 + tc * 4)
                = make_float4(acc[i][0], acc[i][1], acc[i][2], acc[i][3]);
        }
    }
}

// ---------------- kernel 5: weighted combine over top-4 ----------------
__global__ void combine_kernel(float* __restrict__ out) {
    int t = blockIdx.x;
    int h = threadIdx.x * 4;
    float4 acc = make_float4(0.f, 0.f, 0.f, 0.f);
    #pragma unroll
    for (int k = 0; k < TOPK; k++) {
        int   e = g_sel_e[t * TOPK + k];
        int   a = g_off[e] + g_sel_slot[t * TOPK + k];
        float w = g_sel_w[t * TOPK + k];
        float4 v = *(const float4*)(g_down + (size_t)a * HDIM + h);
        acc.x += w * v.x; acc.y += w * v.y;
        acc.z += w * v.z; acc.w += w * v.w;
    }
    *(float4*)(out + (size_t)t * HDIM + h) = acc;
}

// ---------------- launch ----------------
extern "C" void kernel_launch(void* const* d_in, const int* in_sizes, int n_in,
                              void* d_out, int out_size) {
    const float* x   = (const float*)d_in[0];  // [1, 2048, 1024]
    const float* wgt = (const float*)d_in[1];  // [1024, 16]
    const float* wgp = (const float*)d_in[2];  // [16, 1024, 512]
    const float* wup = (const float*)d_in[3];  // [16, 1024, 512]
    const float* wdp = (const float*)d_in[4];  // [16, 512, 1024]
    float* out = (float*)d_out;

    int write_logits = (out_size >= T_TOK * HDIM + T_TOK * NEXP) ? 1 : 0;
    float* logits_out = out + (size_t)T_TOK * HDIM;

    zero_kernel<<<1, 32>>>();
    router_kernel<<<T_TOK / 16, 256>>>(x, wgt, logits_out, write_logits);
    scan_kernel<<<1, 32>>>();
    moe_gemm1<<<dim3(IDIM / 64, T_TOK / 64, NEXP), 256>>>(x, wgp, wup);
    moe_gemm2<<<dim3(HDIM / 64, T_TOK / 64, NEXP), 256>>>(wdp);
    combine_kernel<<<T_TOK, HDIM / 4>>>(out);
}

// round 2
// speedup vs baseline: 2.2521x; 2.2521x over previous
#include <cuda_runtime.h>
#include <math.h>
#include <stdint.h>

#define T_TOK   2048
#define HDIM    1024
#define NEXP    16
#define IDIM    512
#define TOPK    4
#define NASSIGN (T_TOK * TOPK)
#define ROWPAD  128

// ---------------- scratch (static device globals; no allocation) ----------------
__device__ int   g_cnt[NEXP];
__device__ int   g_off[NEXP];
__device__ int   g_tokens[NEXP * T_TOK];
__device__ int   g_sel_e[NASSIGN];
__device__ int   g_sel_slot[NASSIGN];
__device__ float g_sel_w[NASSIGN];
__device__ float g_hidden[(NASSIGN + ROWPAD) * IDIM];
__device__ float g_down[(NASSIGN + ROWPAD) * HDIM];

// ---------------- helpers ----------------
__device__ __forceinline__ unsigned f2tf32(float f) {
    unsigned u;
    asm("cvt.rna.tf32.f32 %0, %1;" : "=r"(u) : "f"(f));
    return u;
}

__device__ __forceinline__ void mma_tf32(float d[4], const unsigned a[4],
                                         unsigned b0, unsigned b1) {
    asm volatile(
        "mma.sync.aligned.m16n8k8.row.col.f32.tf32.tf32.f32 "
        "{%0,%1,%2,%3}, {%4,%5,%6,%7}, {%8,%9}, {%0,%1,%2,%3};"
        : "+f"(d[0]), "+f"(d[1]), "+f"(d[2]), "+f"(d[3])
        : "r"(a[0]), "r"(a[1]), "r"(a[2]), "r"(a[3]), "r"(b0), "r"(b1));
}

// smem layout constants
// A: [kc=2][c=8][m stride 136], kc block = 8*136 + 8 = 1096
#define A_KC   1096
#define A_CS   136
// B: [kc=2][c=8][n stride 72],  kc block = 8*72 + 16 = 592
#define B_KC   592
#define B_CS   72

// ---------------- kernel 0: reset counters ----------------
__global__ void zero_kernel() {
    if (threadIdx.x < NEXP) g_cnt[threadIdx.x] = 0;
}

// ---------------- kernel 1: router (exact fp32) ----------------
__global__ void router_kernel(const float* __restrict__ x,
                              const float* __restrict__ wgt,
                              float* __restrict__ logits_out,
                              int write_logits) {
    __shared__ float sl[16][17];
    int tl = threadIdx.x >> 4;
    int e  = threadIdx.x & 15;
    int t  = blockIdx.x * 16 + tl;

    const float* xr = x + (size_t)t * HDIM;
    float acc = 0.f;
    #pragma unroll 4
    for (int h = 0; h < HDIM; h += 4) {
        float4 xv = *(const float4*)(xr + h);
        acc += xv.x * wgt[(h + 0) * NEXP + e];
        acc += xv.y * wgt[(h + 1) * NEXP + e];
        acc += xv.z * wgt[(h + 2) * NEXP + e];
        acc += xv.w * wgt[(h + 3) * NEXP + e];
    }
    sl[tl][e] = acc;
    if (write_logits) logits_out[(size_t)t * NEXP + e] = acc;
    __syncthreads();

    if (e == 0) {
        float v[NEXP];
        #pragma unroll
        for (int i = 0; i < NEXP; i++) v[i] = sl[tl][i];
        int   sel[TOPK]; float selv[TOPK];
        #pragma unroll
        for (int k = 0; k < TOPK; k++) {
            int bi = 0; float bv = -INFINITY;
            #pragma unroll
            for (int i = 0; i < NEXP; i++)
                if (v[i] > bv) { bv = v[i]; bi = i; }
            sel[k] = bi; selv[k] = bv; v[bi] = -INFINITY;
        }
        float mx = selv[0];
        float ex[TOPK], s = 0.f;
        #pragma unroll
        for (int k = 0; k < TOPK; k++) { ex[k] = expf(selv[k] - mx); s += ex[k]; }
        float inv = 1.f / s;
        #pragma unroll
        for (int k = 0; k < TOPK; k++) {
            int ee   = sel[k];
            int slot = atomicAdd(&g_cnt[ee], 1);
            g_tokens[ee * T_TOK + slot] = t;
            g_sel_e[t * TOPK + k]    = ee;
            g_sel_slot[t * TOPK + k] = slot;
            g_sel_w[t * TOPK + k]    = ex[k] * inv;
        }
    }
}

// ---------------- kernel 2: exclusive scan ----------------
__global__ void scan_kernel() {
    if (threadIdx.x == 0) {
        int o = 0;
        for (int e = 0; e < NEXP; e++) { g_off[e] = o; o += g_cnt[e]; }
    }
}

// ---------------- kernel 3: gate+up tf32 tensor GEMM, fused SiLU*up ----------------
// grid (IDIM/64=8, 16, NEXP), 256 threads; block tile 128m x 64n, BK=16
__global__ __launch_bounds__(256, 2) void moe_gemm1(
        const float* __restrict__ x,
        const float* __restrict__ wg_all,
        const float* __restrict__ wu_all) {
    int e   = blockIdx.z;
    int cnt = g_cnt[e];
    int m0  = blockIdx.y * 128;
    if (m0 >= cnt) return;
    int n0  = blockIdx.x * 64;

    const float* wg = wg_all + (size_t)e * HDIM * IDIM;
    const float* wu = wu_all + (size_t)e * HDIM * IDIM;

    __shared__ unsigned As[2 * A_KC];
    __shared__ unsigned Bg[2 * B_KC];
    __shared__ unsigned Bu[2 * B_KC];
    __shared__ int      stok[128];

    int tid = threadIdx.x;
    if (tid < 128) {
        int m = m0 + tid;
        stok[tid] = (m < cnt) ? g_tokens[e * T_TOK + m] : g_tokens[e * T_TOK];
    }
    __syncthreads();

    int lane = tid & 31, warp = tid >> 5;
    int wm = (warp >> 1) * 32, wn = (warp & 1) * 32;
    int gid = lane >> 2, p = lane & 3;

    // loader mappings
    int arow0 = tid >> 2,          akq0 = tid & 3;
    int arow1 = (tid + 256) >> 2;  // akq1 == akq0
    int bkr = tid >> 4, bnq = tid & 15;

    const float* aptr0 = x + (size_t)stok[arow0] * HDIM + akq0 * 4;
    const float* aptr1 = x + (size_t)stok[arow1] * HDIM + akq0 * 4;
    const float* bgptr = wg + (size_t)bkr * IDIM + n0 + bnq * 4;
    const float* buptr = wu + (size_t)bkr * IDIM + n0 + bnq * 4;

    // STS addresses
    int asts0 = ((akq0 >> 1) * A_KC) + ((akq0 & 1) * 4) * A_CS + arow0;
    int asts1 = ((akq0 >> 1) * A_KC) + ((akq0 & 1) * 4) * A_CS + arow1;
    int bsts  = ((bkr >> 3) * B_KC) + (bkr & 7) * B_CS + bnq * 4;

    float4 aR0 = *(const float4*)aptr0;
    float4 aR1 = *(const float4*)aptr1;
    float4 gR  = *(const float4*)bgptr;
    float4 uR  = *(const float4*)buptr;

    float accg[2][4][4] = {}, accu[2][4][4] = {};

    for (int k0 = 0; k0 < HDIM; k0 += 16) {
        __syncthreads();
        As[asts0 + 0 * A_CS] = f2tf32(aR0.x);
        As[asts0 + 1 * A_CS] = f2tf32(aR0.y);
        As[asts0 + 2 * A_CS] = f2tf32(aR0.z);
        As[asts0 + 3 * A_CS] = f2tf32(aR0.w);
        As[asts1 + 0 * A_CS] = f2tf32(aR1.x);
        As[asts1 + 1 * A_CS] = f2tf32(aR1.y);
        As[asts1 + 2 * A_CS] = f2tf32(aR1.z);
        As[asts1 + 3 * A_CS] = f2tf32(aR1.w);
        *(uint4*)&Bg[bsts] = make_uint4(f2tf32(gR.x), f2tf32(gR.y), f2tf32(gR.z), f2tf32(gR.w));
        *(uint4*)&Bu[bsts] = make_uint4(f2tf32(uR.x), f2tf32(uR.y), f2tf32(uR.z), f2tf32(uR.w));
        __syncthreads();

        if (k0 + 16 < HDIM) {
            aR0 = *(const float4*)(aptr0 + k0 + 16);
            aR1 = *(const float4*)(aptr1 + k0 + 16);
            gR  = *(const float4*)(bgptr + (size_t)(k0 + 16) * IDIM);
            uR  = *(const float4*)(buptr + (size_t)(k0 + 16) * IDIM);
        }

        #pragma unroll
        for (int kc = 0; kc < 2; kc++) {
            unsigned af[2][4];
            int ab = kc * A_KC + p * A_CS;
            #pragma unroll
            for (int mf = 0; mf < 2; mf++) {
                int mm = wm + mf * 16 + gid;
                af[mf][0] = As[ab + mm];
                af[mf][1] = As[ab + mm + 8];
                af[mf][2] = As[ab + 4 * A_CS + mm];
                af[mf][3] = As[ab + 4 * A_CS + mm + 8];
            }
            #pragma unroll
            for (int nf = 0; nf < 4; nf++) {
                int bb = kc * B_KC + p * B_CS + wn + nf * 8 + gid;
                unsigned bg0 = Bg[bb], bg1 = Bg[bb + 4 * B_CS];
                unsigned bu0 = Bu[bb], bu1 = Bu[bb + 4 * B_CS];
                mma_tf32(accg[0][nf], af[0], bg0, bg1);
                mma_tf32(accg[1][nf], af[1], bg0, bg1);
                mma_tf32(accu[0][nf], af[0], bu0, bu1);
                mma_tf32(accu[1][nf], af[1], bu0, bu1);
            }
        }
    }

    // epilogue: silu(g)*u -> g_hidden
    int base = g_off[e] + m0;
    #pragma unroll
    for (int mf = 0; mf < 2; mf++) {
        int r0 = wm + mf * 16 + gid;
        int r1 = r0 + 8;
        #pragma unroll
        for (int nf = 0; nf < 4; nf++) {
            int col = n0 + wn + nf * 8 + 2 * p;
            if (m0 + r0 < cnt) {
                float g0 = accg[mf][nf][0], g1 = accg[mf][nf][1];
                float u0 = accu[mf][nf][0], u1 = accu[mf][nf][1];
                float2 hv = make_float2((g0 / (1.f + __expf(-g0))) * u0,
                                        (g1 / (1.f + __expf(-g1))) * u1);
                *(float2*)(g_hidden + (size_t)(base + r0) * IDIM + col) = hv;
            }
            if (m0 + r1 < cnt) {
                float g2 = accg[mf][nf][2], g3 = accg[mf][nf][3];
                float u2 = accu[mf][nf][2], u3 = accu[mf][nf][3];
                float2 hv = make_float2((g2 / (1.f + __expf(-g2))) * u2,
                                        (g3 / (1.f + __expf(-g3))) * u3);
                *(float2*)(g_hidden + (size_t)(base + r1) * IDIM + col) = hv;
            }
        }
    }
}

// ---------------- kernel 4: down tf32 tensor GEMM ----------------
// grid (HDIM/64=16, 16, NEXP), 256 threads; block tile 128m x 64n, BK=16
__global__ __launch_bounds__(256, 2) void moe_gemm2(const float* __restrict__ wd_all) {
    int e   = blockIdx.z;
    int cnt = g_cnt[e];
    int m0  = blockIdx.y * 128;
    if (m0 >= cnt) return;
    int n0  = blockIdx.x * 64;

    const float* wd = wd_all + (size_t)e * IDIM * HDIM;
    int base = g_off[e] + m0;

    __shared__ unsigned As[2 * A_KC];
    __shared__ unsigned Bs[2 * B_KC];

    int tid = threadIdx.x;
    int lane = tid & 31, warp = tid >> 5;
    int wm = (warp >> 1) * 32, wn = (warp & 1) * 32;
    int gid = lane >> 2, p = lane & 3;

    int arow0 = tid >> 2,          akq0 = tid & 3;
    int arow1 = (tid + 256) >> 2;
    int bkr = tid >> 4, bnq = tid & 15;

    const float* aptr0 = g_hidden + (size_t)(base + arow0) * IDIM + akq0 * 4;
    const float* aptr1 = g_hidden + (size_t)(base + arow1) * IDIM + akq0 * 4;
    const float* bptr  = wd + (size_t)bkr * HDIM + n0 + bnq * 4;

    int asts0 = ((akq0 >> 1) * A_KC) + ((akq0 & 1) * 4) * A_CS + arow0;
    int asts1 = ((akq0 >> 1) * A_KC) + ((akq0 & 1) * 4) * A_CS + arow1;
    int bsts  = ((bkr >> 3) * B_KC) + (bkr & 7) * B_CS + bnq * 4;

    float4 aR0 = *(const float4*)aptr0;
    float4 aR1 = *(const float4*)aptr1;
    float4 bR  = *(const float4*)bptr;

    float acc[2][4][4] = {};

    for (int k0 = 0; k0 < IDIM; k0 += 16) {
        __syncthreads();
        As[asts0 + 0 * A_CS] = f2tf32(aR0.x);
        As[asts0 + 1 * A_CS] = f2tf32(aR0.y);
        As[asts0 + 2 * A_CS] = f2tf32(aR0.z);
        As[asts0 + 3 * A_CS] = f2tf32(aR0.w);
        As[asts1 + 0 * A_CS] = f2tf32(aR1.x);
        As[asts1 + 1 * A_CS] = f2tf32(aR1.y);
        As[asts1 + 2 * A_CS] = f2tf32(aR1.z);
        As[asts1 + 3 * A_CS] = f2tf32(aR1.w);
        *(uint4*)&Bs[bsts] = make_uint4(f2tf32(bR.x), f2tf32(bR.y), f2tf32(bR.z), f2tf32(bR.w));
        __syncthreads();

        if (k0 + 16 < IDIM) {
            aR0 = *(const float4*)(aptr0 + k0 + 16);
            aR1 = *(const float4*)(aptr1 + k0 + 16);
            bR  = *(const float4*)(bptr + (size_t)(k0 + 16) * HDIM);
        }

        #pragma unroll
        for (int kc = 0; kc < 2; kc++) {
            unsigned af[2][4];
            int ab = kc * A_KC + p * A_CS;
            #pragma unroll
            for (int mf = 0; mf < 2; mf++) {
                int mm = wm + mf * 16 + gid;
                af[mf][0] = As[ab + mm];
                af[mf][1] = As[ab + mm + 8];
                af[mf][2] = As[ab + 4 * A_CS + mm];
                af[mf][3] = As[ab + 4 * A_CS + mm + 8];
            }
            #pragma unroll
            for (int nf = 0; nf < 4; nf++) {
                int bb = kc * B_KC + p * B_CS + wn + nf * 8 + gid;
                unsigned b0 = Bs[bb], b1 = Bs[bb + 4 * B_CS];
                mma_tf32(acc[0][nf], af[0], b0, b1);
                mma_tf32(acc[1][nf], af[1], b0, b1);
            }
        }
    }

    #pragma unroll
    for (int mf = 0; mf < 2; mf++) {
        int r0 = wm + mf * 16 + gid;
        int r1 = r0 + 8;
        #pragma unroll
        for (int nf = 0; nf < 4; nf++) {
            int col = n0 + wn + nf * 8 + 2 * p;
            if (m0 + r0 < cnt)
                *(float2*)(g_down + (size_t)(base + r0) * HDIM + col)
                    = make_float2(acc[mf][nf][0], acc[mf][nf][1]);
            if (m0 + r1 < cnt)
                *(float2*)(g_down + (size_t)(base + r1) * HDIM + col)
                    = make_float2(acc[mf][nf][2], acc[mf][nf][3]);
        }
    }
}

// ---------------- kernel 5: weighted combine over top-4 ----------------
__global__ void combine_kernel(float* __restrict__ out) {
    int t = blockIdx.x;
    int h = threadIdx.x * 4;
    float4 acc = make_float4(0.f, 0.f, 0.f, 0.f);
    #pragma unroll
    for (int k = 0; k < TOPK; k++) {
        int   e = g_sel_e[t * TOPK + k];
        int   a = g_off[e] + g_sel_slot[t * TOPK + k];
        float w = g_sel_w[t * TOPK + k];
        float4 v = *(const float4*)(g_down + (size_t)a * HDIM + h);
        acc.x += w * v.x; acc.y += w * v.y;
        acc.z += w * v.z; acc.w += w * v.w;
    }
    *(float4*)(out + (size_t)t * HDIM + h) = acc;
}

// ---------------- launch ----------------
extern "C" void kernel_launch(void* const* d_in, const int* in_sizes, int n_in,
                              void* d_out, int out_size) {
    const float* x   = (const float*)d_in[0];
    const float* wgt = (const float*)d_in[1];
    const float* wgp = (const float*)d_in[2];
    const float* wup = (const float*)d_in[3];
    const float* wdp = (const float*)d_in[4];
    float* out = (float*)d_out;

    int write_logits = (out_size >= T_TOK * HDIM + T_TOK * NEXP) ? 1 : 0;
    float* logits_out = out + (size_t)T_TOK * HDIM;

    zero_kernel<<<1, 32>>>();
    router_kernel<<<T_TOK / 16, 256>>>(x, wgt, logits_out, write_logits);
    scan_kernel<<<1, 32>>>();
    moe_gemm1<<<dim3(IDIM / 64, T_TOK / 128, NEXP), 256>>>(x, wgp, wup);
    moe_gemm2<<<dim3(HDIM / 64, T_TOK / 128, NEXP), 256>>>(wdp);
    combine_kernel<<<T_TOK, HDIM / 4>>>(out);
}

// round 3
// speedup vs baseline: 2.2720x; 1.0088x over previous
#include <cuda_runtime.h>
#include <math.h>
#include <stdint.h>

#define T_TOK   2048
#define HDIM    1024
#define NEXP    16
#define IDIM    512
#define TOPK    4
#define NASSIGN (T_TOK * TOPK)
#define ROWPAD  128

// ---------------- scratch (static device globals; no allocation) ----------------
__device__ int   g_cnt[NEXP];
__device__ int   g_off[NEXP];
__device__ int   g_tokens[NEXP * T_TOK];
__device__ int   g_sel_e[NASSIGN];
__device__ int   g_sel_slot[NASSIGN];
__device__ float g_sel_w[NASSIGN];
__device__ float g_hidden[(NASSIGN + ROWPAD) * IDIM];
__device__ float g_down[(NASSIGN + ROWPAD) * HDIM];

// ---------------- helpers ----------------
__device__ __forceinline__ unsigned f2tf32(float f) {
    unsigned u;
    asm("cvt.rna.tf32.f32 %0, %1;" : "=r"(u) : "f"(f));
    return u;
}

__device__ __forceinline__ void mma_tf32(float d[4], const unsigned a[4],
                                         unsigned b0, unsigned b1) {
    asm volatile(
        "mma.sync.aligned.m16n8k8.row.col.f32.tf32.tf32.f32 "
        "{%0,%1,%2,%3}, {%4,%5,%6,%7}, {%8,%9}, {%0,%1,%2,%3};"
        : "+f"(d[0]), "+f"(d[1]), "+f"(d[2]), "+f"(d[3])
        : "r"(a[0]), "r"(a[1]), "r"(a[2]), "r"(a[3]), "r"(b0), "r"(b1));
}

// smem layout constants
// A: [kc=2][c=8][m stride 136], kc block = 8*136 + 8 = 1096
#define A_KC   1096
#define A_CS   136
// B: [kc=2][c=8][n stride 72],  kc block = 8*72 + 16 = 592
#define B_KC   592
#define B_CS   72

// ---------------- kernel 0: reset counters ----------------
__global__ void zero_kernel() {
    if (threadIdx.x < NEXP) g_cnt[threadIdx.x] = 0;
}

// ---------------- kernel 1: router (exact fp32) ----------------
__global__ void router_kernel(const float* __restrict__ x,
                              const float* __restrict__ wgt,
                              float* __restrict__ logits_out,
                              int write_logits) {
    __shared__ float sl[16][17];
    int tl = threadIdx.x >> 4;
    int e  = threadIdx.x & 15;
    int t  = blockIdx.x * 16 + tl;

    const float* xr = x + (size_t)t * HDIM;
    float acc = 0.f;
    #pragma unroll 4
    for (int h = 0; h < HDIM; h += 4) {
        float4 xv = *(const float4*)(xr + h);
        acc += xv.x * wgt[(h + 0) * NEXP + e];
        acc += xv.y * wgt[(h + 1) * NEXP + e];
        acc += xv.z * wgt[(h + 2) * NEXP + e];
        acc += xv.w * wgt[(h + 3) * NEXP + e];
    }
    sl[tl][e] = acc;
    if (write_logits) logits_out[(size_t)t * NEXP + e] = acc;
    __syncthreads();

    if (e == 0) {
        float v[NEXP];
        #pragma unroll
        for (int i = 0; i < NEXP; i++) v[i] = sl[tl][i];
        int   sel[TOPK]; float selv[TOPK];
        #pragma unroll
        for (int k = 0; k < TOPK; k++) {
            int bi = 0; float bv = -INFINITY;
            #pragma unroll
            for (int i = 0; i < NEXP; i++)
                if (v[i] > bv) { bv = v[i]; bi = i; }
            sel[k] = bi; selv[k] = bv; v[bi] = -INFINITY;
        }
        float mx = selv[0];
        float ex[TOPK], s = 0.f;
        #pragma unroll
        for (int k = 0; k < TOPK; k++) { ex[k] = expf(selv[k] - mx); s += ex[k]; }
        float inv = 1.f / s;
        #pragma unroll
        for (int k = 0; k < TOPK; k++) {
            int ee   = sel[k];
            int slot = atomicAdd(&g_cnt[ee], 1);
            g_tokens[ee * T_TOK + slot] = t;
            g_sel_e[t * TOPK + k]    = ee;
            g_sel_slot[t * TOPK + k] = slot;
            g_sel_w[t * TOPK + k]    = ex[k] * inv;
        }
    }
}

// ---------------- kernel 2: exclusive scan ----------------
__global__ void scan_kernel() {
    if (threadIdx.x == 0) {
        int o = 0;
        for (int e = 0; e < NEXP; e++) { g_off[e] = o; o += g_cnt[e]; }
    }
}

// ---------------- kernel 3: gate+up tf32 tensor GEMM, fused SiLU*up ----------------
// grid (IDIM/64=8, 16, NEXP), 256 threads; block tile 128m x 64n, BK=16
__global__ __launch_bounds__(256, 2) void moe_gemm1(
        const float* __restrict__ x,
        const float* __restrict__ wg_all,
        const float* __restrict__ wu_all) {
    int e   = blockIdx.z;
    int cnt = g_cnt[e];
    int m0  = blockIdx.y * 128;
    if (m0 >= cnt) return;
    int n0  = blockIdx.x * 64;

    const float* wg = wg_all + (size_t)e * HDIM * IDIM;
    const float* wu = wu_all + (size_t)e * HDIM * IDIM;

    __shared__ unsigned As[2 * A_KC];
    __shared__ unsigned Bg[2 * B_KC];
    __shared__ unsigned Bu[2 * B_KC];
    __shared__ int      stok[128];

    int tid = threadIdx.x;
    if (tid < 128) {
        int m = m0 + tid;
        stok[tid] = (m < cnt) ? g_tokens[e * T_TOK + m] : g_tokens[e * T_TOK];
    }
    __syncthreads();

    int lane = tid & 31, warp = tid >> 5;
    int wm = (warp >> 1) * 32, wn = (warp & 1) * 32;
    int gid = lane >> 2, p = lane & 3;

    // loader mappings
    int arow0 = tid >> 2,          akq0 = tid & 3;
    int arow1 = (tid + 256) >> 2;  // akq1 == akq0
    int bkr = tid >> 4, bnq = tid & 15;

    const float* aptr0 = x + (size_t)stok[arow0] * HDIM + akq0 * 4;
    const float* aptr1 = x + (size_t)stok[arow1] * HDIM + akq0 * 4;
    const float* bgptr = wg + (size_t)bkr * IDIM + n0 + bnq * 4;
    const float* buptr = wu + (size_t)bkr * IDIM + n0 + bnq * 4;

    // STS addresses
    int asts0 = ((akq0 >> 1) * A_KC) + ((akq0 & 1) * 4) * A_CS + arow0;
    int asts1 = ((akq0 >> 1) * A_KC) + ((akq0 & 1) * 4) * A_CS + arow1;
    int bsts  = ((bkr >> 3) * B_KC) + (bkr & 7) * B_CS + bnq * 4;

    float4 aR0 = *(const float4*)aptr0;
    float4 aR1 = *(const float4*)aptr1;
    float4 gR  = *(const float4*)bgptr;
    float4 uR  = *(const float4*)buptr;

    float accg[2][4][4] = {}, accu[2][4][4] = {};

    for (int k0 = 0; k0 < HDIM; k0 += 16) {
        __syncthreads();
        As[asts0 + 0 * A_CS] = f2tf32(aR0.x);
        As[asts0 + 1 * A_CS] = f2tf32(aR0.y);
        As[asts0 + 2 * A_CS] = f2tf32(aR0.z);
        As[asts0 + 3 * A_CS] = f2tf32(aR0.w);
        As[asts1 + 0 * A_CS] = f2tf32(aR1.x);
        As[asts1 + 1 * A_CS] = f2tf32(aR1.y);
        As[asts1 + 2 * A_CS] = f2tf32(aR1.z);
        As[asts1 + 3 * A_CS] = f2tf32(aR1.w);
        *(uint4*)&Bg[bsts] = make_uint4(f2tf32(gR.x), f2tf32(gR.y), f2tf32(gR.z), f2tf32(gR.w));
        *(uint4*)&Bu[bsts] = make_uint4(f2tf32(uR.x), f2tf32(uR.y), f2tf32(uR.z), f2tf32(uR.w));
        __syncthreads();

        if (k0 + 16 < HDIM) {
            aR0 = *(const float4*)(aptr0 + k0 + 16);
            aR1 = *(const float4*)(aptr1 + k0 + 16);
            gR  = *(const float4*)(bgptr + (size_t)(k0 + 16) * IDIM);
            uR  = *(const float4*)(buptr + (size_t)(k0 + 16) * IDIM);
        }

        #pragma unroll
        for (int kc = 0; kc < 2; kc++) {
            unsigned af[2][4];
            int ab = kc * A_KC + p * A_CS;
            #pragma unroll
            for (int mf = 0; mf < 2; mf++) {
                int mm = wm + mf * 16 + gid;
                af[mf][0] = As[ab + mm];
                af[mf][1] = As[ab + mm + 8];
                af[mf][2] = As[ab + 4 * A_CS + mm];
                af[mf][3] = As[ab + 4 * A_CS + mm + 8];
            }
            #pragma unroll
            for (int nf = 0; nf < 4; nf++) {
                int bb = kc * B_KC + p * B_CS + wn + nf * 8 + gid;
                unsigned bg0 = Bg[bb], bg1 = Bg[bb + 4 * B_CS];
                unsigned bu0 = Bu[bb], bu1 = Bu[bb + 4 * B_CS];
                mma_tf32(accg[0][nf], af[0], bg0, bg1);
                mma_tf32(accg[1][nf], af[1], bg0, bg1);
                mma_tf32(accu[0][nf], af[0], bu0, bu1);
                mma_tf32(accu[1][nf], af[1], bu0, bu1);
            }
        }
    }

    // epilogue: silu(g)*u -> g_hidden
    int base = g_off[e] + m0;
    #pragma unroll
    for (int mf = 0; mf < 2; mf++) {
        int r0 = wm + mf * 16 + gid;
        int r1 = r0 + 8;
        #pragma unroll
        for (int nf = 0; nf < 4; nf++) {
            int col = n0 + wn + nf * 8 + 2 * p;
            if (m0 + r0 < cnt) {
                float g0 = accg[mf][nf][0], g1 = accg[mf][nf][1];
                float u0 = accu[mf][nf][0], u1 = accu[mf][nf][1];
                float2 hv = make_float2((g0 / (1.f + __expf(-g0))) * u0,
                                        (g1 / (1.f + __expf(-g1))) * u1);
                *(float2*)(g_hidden + (size_t)(base + r0) * IDIM + col) = hv;
            }
            if (m0 + r1 < cnt) {
                float g2 = accg[mf][nf][2], g3 = accg[mf][nf][3];
                float u2 = accu[mf][nf][2], u3 = accu[mf][nf][3];
                float2 hv = make_float2((g2 / (1.f + __expf(-g2))) * u2,
                                        (g3 / (1.f + __expf(-g3))) * u3);
                *(float2*)(g_hidden + (size_t)(base + r1) * IDIM + col) = hv;
            }
        }
    }
}

// ---------------- kernel 4: down tf32 tensor GEMM ----------------
// grid (HDIM/64=16, 16, NEXP), 256 threads; block tile 128m x 64n, BK=16
__global__ __launch_bounds__(256, 2) void moe_gemm2(const float* __restrict__ wd_all) {
    int e   = blockIdx.z;
    int cnt = g_cnt[e];
    int m0  = blockIdx.y * 128;
    if (m0 >= cnt) return;
    int n0  = blockIdx.x * 64;

    const float* wd = wd_all + (size_t)e * IDIM * HDIM;
    int base = g_off[e] + m0;

    __shared__ unsigned As[2 * A_KC];
    __shared__ unsigned Bs[2 * B_KC];

    int tid = threadIdx.x;
    int lane = tid & 31, warp = tid >> 5;
    int wm = (warp >> 1) * 32, wn = (warp & 1) * 32;
    int gid = lane >> 2, p = lane & 3;

    int arow0 = tid >> 2,          akq0 = tid & 3;
    int arow1 = (tid + 256) >> 2;
    int bkr = tid >> 4, bnq = tid & 15;

    const float* aptr0 = g_hidden + (size_t)(base + arow0) * IDIM + akq0 * 4;
    const float* aptr1 = g_hidden + (size_t)(base + arow1) * IDIM + akq0 * 4;
    const float* bptr  = wd + (size_t)bkr * HDIM + n0 + bnq * 4;

    int asts0 = ((akq0 >> 1) * A_KC) + ((akq0 & 1) * 4) * A_CS + arow0;
    int asts1 = ((akq0 >> 1) * A_KC) + ((akq0 & 1) * 4) * A_CS + arow1;
    int bsts  = ((bkr >> 3) * B_KC) + (bkr & 7) * B_CS + bnq * 4;

    float4 aR0 = *(const float4*)aptr0;
    float4 aR1 = *(const float4*)aptr1;
    float4 bR  = *(const float4*)bptr;

    float acc[2][4][4] = {};

    for (int k0 = 0; k0 < IDIM; k0 += 16) {
        __syncthreads();
        As[asts0 + 0 * A_CS] = f2tf32(aR0.x);
        As[asts0 + 1 * A_CS] = f2tf32(aR0.y);
        As[asts0 + 2 * A_CS] = f2tf32(aR0.z);
        As[asts0 + 3 * A_CS] = f2tf32(aR0.w);
        As[asts1 + 0 * A_CS] = f2tf32(aR1.x);
        As[asts1 + 1 * A_CS] = f2tf32(aR1.y);
        As[asts1 + 2 * A_CS] = f2tf32(aR1.z);
        As[asts1 + 3 * A_CS] = f2tf32(aR1.w);
        *(uint4*)&Bs[bsts] = make_uint4(f2tf32(bR.x), f2tf32(bR.y), f2tf32(bR.z), f2tf32(bR.w));
        __syncthreads();

        if (k0 + 16 < IDIM) {
            aR0 = *(const float4*)(aptr0 + k0 + 16);
            aR1 = *(const float4*)(aptr1 + k0 + 16);
            bR  = *(const float4*)(bptr + (size_t)(k0 + 16) * HDIM);
        }

        #pragma unroll
        for (int kc = 0; kc < 2; kc++) {
            unsigned af[2][4];
            int ab = kc * A_KC + p * A_CS;
            #pragma unroll
            for (int mf = 0; mf < 2; mf++) {
                int mm = wm + mf * 16 + gid;
                af[mf][0] = As[ab + mm];
                af[mf][1] = As[ab + mm + 8];
                af[mf][2] = As[ab + 4 * A_CS + mm];
                af[mf][3] = As[ab + 4 * A_CS + mm + 8];
            }
            #pragma unroll
            for (int nf = 0; nf < 4; nf++) {
                int bb = kc * B_KC + p * B_CS + wn + nf * 8 + gid;
                unsigned b0 = Bs[bb], b1 = Bs[bb + 4 * B_CS];
                mma_tf32(acc[0][nf], af[0], b0, b1);
                mma_tf32(acc[1][nf], af[1], b0, b1);
            }
        }
    }

    #pragma unroll
    for (int mf = 0; mf < 2; mf++) {
        int r0 = wm + mf * 16 + gid;
        int r1 = r0 + 8;
        #pragma unroll
        for (int nf = 0; nf < 4; nf++) {
            int col = n0 + wn + nf * 8 + 2 * p;
            if (m0 + r0 < cnt)
                *(float2*)(g_down + (size_t)(base + r0) * HDIM + col)
                    = make_float2(acc[mf][nf][0], acc[mf][nf][1]);
            if (m0 + r1 < cnt)
                *(float2*)(g_down + (size_t)(base + r1) * HDIM + col)
                    = make_float2(acc[mf][nf][2], acc[mf][nf][3]);
        }
    }
}

// ---------------- kernel 5: weighted combine over top-4 ----------------
__global__ void combine_kernel(float* __restrict__ out) {
    int t = blockIdx.x;
    int h = threadIdx.x * 4;
    float4 acc = make_float4(0.f, 0.f, 0.f, 0.f);
    #pragma unroll
    for (int k = 0; k < TOPK; k++) {
        int   e = g_sel_e[t * TOPK + k];
        int   a = g_off[e] + g_sel_slot[t * TOPK + k];
        float w = g_sel_w[t * TOPK + k];
        float4 v = *(const float4*)(g_down + (size_t)a * HDIM + h);
        acc.x += w * v.x; acc.y += w * v.y;
        acc.z += w * v.z; acc.w += w * v.w;
    }
    *(float4*)(out + (size_t)t * HDIM + h) = acc;
}

// ---------------- launch ----------------
extern "C" void kernel_launch(void* const* d_in, const int* in_sizes, int n_in,
                              void* d_out, int out_size) {
    const float* x   = (const float*)d_in[0];
    const float* wgt = (const float*)d_in[1];
    const float* wgp = (const float*)d_in[2];
    const float* wup = (const float*)d_in[3];
    const float* wdp = (const float*)d_in[4];
    float* out = (float*)d_out;

    int write_logits = (out_size >= T_TOK * HDIM + T_TOK * NEXP) ? 1 : 0;
    float* logits_out = out + (size_t)T_TOK * HDIM;

    zero_kernel<<<1, 32>>>();
    router_kernel<<<T_TOK / 16, 256>>>(x, wgt, logits_out, write_logits);
    scan_kernel<<<1, 32>>>();
    moe_gemm1<<<dim3(IDIM / 64, T_TOK / 128, NEXP), 256>>>(x, wgp, wup);
    moe_gemm2<<<dim3(HDIM / 64, T_TOK / 128, NEXP), 256>>>(wdp);
    combine_kernel<<<T_TOK, HDIM / 4>>>(out);
}

// round 5
// speedup vs baseline: 2.2839x; 1.0052x over previous
#include <cuda_runtime.h>
#include <math.h>
#include <stdint.h>

#define T_TOK   2048
#define HDIM    1024
#define NEXP    16
#define IDIM    512
#define TOPK    4
#define NASSIGN (T_TOK * TOPK)
#define ROWPAD  128

// ---------------- scratch ----------------
__device__ int   g_cnt[NEXP];
__device__ int   g_off[NEXP];
__device__ int   g_tokens[NEXP * T_TOK];
__device__ int   g_sel_e[NASSIGN];
__device__ int   g_sel_slot[NASSIGN];
__device__ float g_sel_w[NASSIGN];
__device__ float g_hidden[(NASSIGN + ROWPAD) * IDIM];
__device__ float g_down[(NASSIGN + ROWPAD) * HDIM];

// ---------------- helpers ----------------
__device__ __forceinline__ unsigned f2tf32(float f) {
    unsigned u;
    asm("cvt.rna.tf32.f32 %0, %1;" : "=r"(u) : "f"(f));
    return u;
}

__device__ __forceinline__ void mma_tf32(float d[4], const unsigned a[4],
                                         unsigned b0, unsigned b1) {
    asm volatile(
        "mma.sync.aligned.m16n8k8.row.col.f32.tf32.tf32.f32 "
        "{%0,%1,%2,%3}, {%4,%5,%6,%7}, {%8,%9}, {%0,%1,%2,%3};"
        : "+f"(d[0]), "+f"(d[1]), "+f"(d[2]), "+f"(d[3])
        : "r"(a[0]), "r"(a[1]), "r"(a[2]), "r"(a[3]), "r"(b0), "r"(b1));
}

// smem layout constants (per stage)
// A: [kc=2][c=8][m stride 136], kc block = 8*136 + 8 = 1096
#define A_KC   1096
#define A_CS   136
#define A_SZ   (2 * A_KC)
// B: [kc=2][c=8][n stride 72],  kc block = 8*72 + 16 = 592
#define B_KC   592
#define B_CS   72
#define B_SZ   (2 * B_KC)

// ---------------- kernel 0: reset counters ----------------
__global__ void zero_kernel() {
    if (threadIdx.x < NEXP) g_cnt[threadIdx.x] = 0;
}

// ---------------- kernel 1: router (exact fp32) ----------------
__global__ void router_kernel(const float* __restrict__ x,
                              const float* __restrict__ wgt,
                              float* __restrict__ logits_out,
                              int write_logits) {
    __shared__ float sl[16][17];
    int tl = threadIdx.x >> 4;
    int e  = threadIdx.x & 15;
    int t  = blockIdx.x * 16 + tl;

    const float* xr = x + (size_t)t * HDIM;
    float acc = 0.f;
    #pragma unroll 4
    for (int h = 0; h < HDIM; h += 4) {
        float4 xv = *(const float4*)(xr + h);
        acc += xv.x * wgt[(h + 0) * NEXP + e];
        acc += xv.y * wgt[(h + 1) * NEXP + e];
        acc += xv.z * wgt[(h + 2) * NEXP + e];
        acc += xv.w * wgt[(h + 3) * NEXP + e];
    }
    sl[tl][e] = acc;
    if (write_logits) logits_out[(size_t)t * NEXP + e] = acc;
    __syncthreads();

    if (e == 0) {
        float v[NEXP];
        #pragma unroll
        for (int i = 0; i < NEXP; i++) v[i] = sl[tl][i];
        int   sel[TOPK]; float selv[TOPK];
        #pragma unroll
        for (int k = 0; k < TOPK; k++) {
            int bi = 0; float bv = -INFINITY;
            #pragma unroll
            for (int i = 0; i < NEXP; i++)
                if (v[i] > bv) { bv = v[i]; bi = i; }
            sel[k] = bi; selv[k] = bv; v[bi] = -INFINITY;
        }
        float mx = selv[0];
        float ex[TOPK], s = 0.f;
        #pragma unroll
        for (int k = 0; k < TOPK; k++) { ex[k] = expf(selv[k] - mx); s += ex[k]; }
        float inv = 1.f / s;
        #pragma unroll
        for (int k = 0; k < TOPK; k++) {
            int ee   = sel[k];
            int slot = atomicAdd(&g_cnt[ee], 1);
            g_tokens[ee * T_TOK + slot] = t;
            g_sel_e[t * TOPK + k]    = ee;
            g_sel_slot[t * TOPK + k] = slot;
            g_sel_w[t * TOPK + k]    = ex[k] * inv;
        }
    }
}

// ---------------- kernel 2: exclusive scan ----------------
__global__ void scan_kernel() {
    if (threadIdx.x == 0) {
        int o = 0;
        for (int e = 0; e < NEXP; e++) { g_off[e] = o; o += g_cnt[e]; }
    }
}

// ======== gemm1: tf32 mma.sync, double-buffered smem, fused SiLU*up ========
// grid (IDIM/64=8, 16, NEXP), 256 threads; block tile 128m x 64n, BK=16
__global__ __launch_bounds__(256, 2) void moe_gemm1(
        const float* __restrict__ x,
        const float* __restrict__ wg_all,
        const float* __restrict__ wu_all) {
    int e   = blockIdx.z;
    int cnt = g_cnt[e];
    int m0  = blockIdx.y * 128;
    if (m0 >= cnt) return;
    int n0  = blockIdx.x * 64;

    const float* wg = wg_all + (size_t)e * HDIM * IDIM;
    const float* wu = wu_all + (size_t)e * HDIM * IDIM;

    __shared__ unsigned As[2 * A_SZ];
    __shared__ unsigned Bg[2 * B_SZ];
    __shared__ unsigned Bu[2 * B_SZ];
    __shared__ int      stok[128];

    int tid = threadIdx.x;
    if (tid < 128) {
        int m = m0 + tid;
        stok[tid] = (m < cnt) ? g_tokens[e * T_TOK + m] : g_tokens[e * T_TOK];
    }
    __syncthreads();

    int lane = tid & 31, warp = tid >> 5;
    int wm = (warp >> 1) * 32, wn = (warp & 1) * 32;
    int gid = lane >> 2, p = lane & 3;

    // loader mappings
    int arow0 = tid >> 2,          akq0 = tid & 3;
    int arow1 = (tid + 256) >> 2;
    int bkr = tid >> 4, bnq = tid & 15;

    const float* aptr0 = x + (size_t)stok[arow0] * HDIM + akq0 * 4;
    const float* aptr1 = x + (size_t)stok[arow1] * HDIM + akq0 * 4;
    const float* bgptr = wg + (size_t)bkr * IDIM + n0 + bnq * 4;
    const float* buptr = wu + (size_t)bkr * IDIM + n0 + bnq * 4;

    int asts0 = ((akq0 >> 1) * A_KC) + ((akq0 & 1) * 4) * A_CS + arow0;
    int asts1 = ((akq0 >> 1) * A_KC) + ((akq0 & 1) * 4) * A_CS + arow1;
    int bsts  = ((bkr >> 3) * B_KC) + (bkr & 7) * B_CS + bnq * 4;

    float accg[2][4][4] = {}, accu[2][4][4] = {};

    // prologue: load + store stage 0
    {
        float4 aR0 = *(const float4*)aptr0;
        float4 aR1 = *(const float4*)aptr1;
        float4 gR  = *(const float4*)bgptr;
        float4 uR  = *(const float4*)buptr;
        As[asts0 + 0 * A_CS] = f2tf32(aR0.x);
        As[asts0 + 1 * A_CS] = f2tf32(aR0.y);
        As[asts0 + 2 * A_CS] = f2tf32(aR0.z);
        As[asts0 + 3 * A_CS] = f2tf32(aR0.w);
        As[asts1 + 0 * A_CS] = f2tf32(aR1.x);
        As[asts1 + 1 * A_CS] = f2tf32(aR1.y);
        As[asts1 + 2 * A_CS] = f2tf32(aR1.z);
        As[asts1 + 3 * A_CS] = f2tf32(aR1.w);
        *(uint4*)&Bg[bsts] = make_uint4(f2tf32(gR.x), f2tf32(gR.y), f2tf32(gR.z), f2tf32(gR.w));
        *(uint4*)&Bu[bsts] = make_uint4(f2tf32(uR.x), f2tf32(uR.y), f2tf32(uR.z), f2tf32(uR.w));
    }
    __syncthreads();

    #pragma unroll 1
    for (int it = 0; it < HDIM / 16; it++) {
        int s = it & 1;
        int sa = s * A_SZ, sb = s * B_SZ;

        float4 aR0, aR1, gR, uR;
        bool more = (it + 1) < HDIM / 16;
        if (more) {
            int k0 = (it + 1) * 16;
            aR0 = *(const float4*)(aptr0 + k0);
            aR1 = *(const float4*)(aptr1 + k0);
            gR  = *(const float4*)(bgptr + (size_t)k0 * IDIM);
            uR  = *(const float4*)(buptr + (size_t)k0 * IDIM);
        }

        #pragma unroll
        for (int kc = 0; kc < 2; kc++) {
            unsigned af[2][4];
            int ab = sa + kc * A_KC + p * A_CS;
            #pragma unroll
            for (int mf = 0; mf < 2; mf++) {
                int mm = wm + mf * 16 + gid;
                af[mf][0] = As[ab + mm];
                af[mf][1] = As[ab + mm + 8];
                af[mf][2] = As[ab + 4 * A_CS + mm];
                af[mf][3] = As[ab + 4 * A_CS + mm + 8];
            }
            #pragma unroll
            for (int nf = 0; nf < 4; nf++) {
                int bb = sb + kc * B_KC + p * B_CS + wn + nf * 8 + gid;
                unsigned bg0 = Bg[bb], bg1 = Bg[bb + 4 * B_CS];
                unsigned bu0 = Bu[bb], bu1 = Bu[bb + 4 * B_CS];
                mma_tf32(accg[0][nf], af[0], bg0, bg1);
                mma_tf32(accg[1][nf], af[1], bg0, bg1);
                mma_tf32(accu[0][nf], af[0], bu0, bu1);
                mma_tf32(accu[1][nf], af[1], bu0, bu1);
            }
        }

        if (more) {
            int na = (s ^ 1) * A_SZ, nb = (s ^ 1) * B_SZ;
            As[na + asts0 + 0 * A_CS] = f2tf32(aR0.x);
            As[na + asts0 + 1 * A_CS] = f2tf32(aR0.y);
            As[na + asts0 + 2 * A_CS] = f2tf32(aR0.z);
            As[na + asts0 + 3 * A_CS] = f2tf32(aR0.w);
            As[na + asts1 + 0 * A_CS] = f2tf32(aR1.x);
            As[na + asts1 + 1 * A_CS] = f2tf32(aR1.y);
            As[na + asts1 + 2 * A_CS] = f2tf32(aR1.z);
            As[na + asts1 + 3 * A_CS] = f2tf32(aR1.w);
            *(uint4*)&Bg[nb + bsts] = make_uint4(f2tf32(gR.x), f2tf32(gR.y), f2tf32(gR.z), f2tf32(gR.w));
            *(uint4*)&Bu[nb + bsts] = make_uint4(f2tf32(uR.x), f2tf32(uR.y), f2tf32(uR.z), f2tf32(uR.w));
        }
        __syncthreads();
    }

    // epilogue: silu(g)*u -> g_hidden
    int base = g_off[e] + m0;
    #pragma unroll
    for (int mf = 0; mf < 2; mf++) {
        int r0 = wm + mf * 16 + gid;
        int r1 = r0 + 8;
        #pragma unroll
        for (int nf = 0; nf < 4; nf++) {
            int col = n0 + wn + nf * 8 + 2 * p;
            if (m0 + r0 < cnt) {
                float g0 = accg[mf][nf][0], g1 = accg[mf][nf][1];
                float u0 = accu[mf][nf][0], u1 = accu[mf][nf][1];
                float2 hv = make_float2((g0 / (1.f + __expf(-g0))) * u0,
                                        (g1 / (1.f + __expf(-g1))) * u1);
                *(float2*)(g_hidden + (size_t)(base + r0) * IDIM + col) = hv;
            }
            if (m0 + r1 < cnt) {
                float g2 = accg[mf][nf][2], g3 = accg[mf][nf][3];
                float u2 = accu[mf][nf][2], u3 = accu[mf][nf][3];
                float2 hv = make_float2((g2 / (1.f + __expf(-g2))) * u2,
                                        (g3 / (1.f + __expf(-g3))) * u3);
                *(float2*)(g_hidden + (size_t)(base + r1) * IDIM + col) = hv;
            }
        }
    }
}

// ======== gemm2: tf32 mma.sync, double-buffered smem, down proj ========
// grid (HDIM/64=16, 16, NEXP), 256 threads; block tile 128m x 64n, BK=16
__global__ __launch_bounds__(256, 2) void moe_gemm2(const float* __restrict__ wd_all) {
    int e   = blockIdx.z;
    int cnt = g_cnt[e];
    int m0  = blockIdx.y * 128;
    if (m0 >= cnt) return;
    int n0  = blockIdx.x * 64;

    const float* wd = wd_all + (size_t)e * IDIM * HDIM;
    int base = g_off[e] + m0;

    __shared__ unsigned As[2 * A_SZ];
    __shared__ unsigned Bs[2 * B_SZ];

    int tid = threadIdx.x;
    int lane = tid & 31, warp = tid >> 5;
    int wm = (warp >> 1) * 32, wn = (warp & 1) * 32;
    int gid = lane >> 2, p = lane & 3;

    int arow0 = tid >> 2,          akq0 = tid & 3;
    int arow1 = (tid + 256) >> 2;
    int bkr = tid >> 4, bnq = tid & 15;

    const float* aptr0 = g_hidden + (size_t)(base + arow0) * IDIM + akq0 * 4;
    const float* aptr1 = g_hidden + (size_t)(base + arow1) * IDIM + akq0 * 4;
    const float* bptr  = wd + (size_t)bkr * HDIM + n0 + bnq * 4;

    int asts0 = ((akq0 >> 1) * A_KC) + ((akq0 & 1) * 4) * A_CS + arow0;
    int asts1 = ((akq0 >> 1) * A_KC) + ((akq0 & 1) * 4) * A_CS + arow1;
    int bsts  = ((bkr >> 3) * B_KC) + (bkr & 7) * B_CS + bnq * 4;

    float acc[2][4][4] = {};

    {
        float4 aR0 = *(const float4*)aptr0;
        float4 aR1 = *(const float4*)aptr1;
        float4 bR  = *(const float4*)bptr;
        As[asts0 + 0 * A_CS] = f2tf32(aR0.x);
        As[asts0 + 1 * A_CS] = f2tf32(aR0.y);
        As[asts0 + 2 * A_CS] = f2tf32(aR0.z);
        As[asts0 + 3 * A_CS] = f2tf32(aR0.w);
        As[asts1 + 0 * A_CS] = f2tf32(aR1.x);
        As[asts1 + 1 * A_CS] = f2tf32(aR1.y);
        As[asts1 + 2 * A_CS] = f2tf32(aR1.z);
        As[asts1 + 3 * A_CS] = f2tf32(aR1.w);
        *(uint4*)&Bs[bsts] = make_uint4(f2tf32(bR.x), f2tf32(bR.y), f2tf32(bR.z), f2tf32(bR.w));
    }
    __syncthreads();

    #pragma unroll 1
    for (int it = 0; it < IDIM / 16; it++) {
        int s = it & 1;
        int sa = s * A_SZ, sb = s * B_SZ;

        float4 aR0, aR1, bR;
        bool more = (it + 1) < IDIM / 16;
        if (more) {
            int k0 = (it + 1) * 16;
            aR0 = *(const float4*)(aptr0 + k0);
            aR1 = *(const float4*)(aptr1 + k0);
            bR  = *(const float4*)(bptr + (size_t)k0 * HDIM);
        }

        #pragma unroll
        for (int kc = 0; kc < 2; kc++) {
            unsigned af[2][4];
            int ab = sa + kc * A_KC + p * A_CS;
            #pragma unroll
            for (int mf = 0; mf < 2; mf++) {
                int mm = wm + mf * 16 + gid;
                af[mf][0] = As[ab + mm];
                af[mf][1] = As[ab + mm + 8];
                af[mf][2] = As[ab + 4 * A_CS + mm];
                af[mf][3] = As[ab + 4 * A_CS + mm + 8];
            }
            #pragma unroll
            for (int nf = 0; nf < 4; nf++) {
                int bb = sb + kc * B_KC + p * B_CS + wn + nf * 8 + gid;
                unsigned b0 = Bs[bb], b1 = Bs[bb + 4 * B_CS];
                mma_tf32(acc[0][nf], af[0], b0, b1);
                mma_tf32(acc[1][nf], af[1], b0, b1);
            }
        }

        if (more) {
            int na = (s ^ 1) * A_SZ, nb = (s ^ 1) * B_SZ;
            As[na + asts0 + 0 * A_CS] = f2tf32(aR0.x);
            As[na + asts0 + 1 * A_CS] = f2tf32(aR0.y);
            As[na + asts0 + 2 * A_CS] = f2tf32(aR0.z);
            As[na + asts0 + 3 * A_CS] = f2tf32(aR0.w);
            As[na + asts1 + 0 * A_CS] = f2tf32(aR1.x);
            As[na + asts1 + 1 * A_CS] = f2tf32(aR1.y);
            As[na + asts1 + 2 * A_CS] = f2tf32(aR1.z);
            As[na + asts1 + 3 * A_CS] = f2tf32(aR1.w);
            *(uint4*)&Bs[nb + bsts] = make_uint4(f2tf32(bR.x), f2tf32(bR.y), f2tf32(bR.z), f2tf32(bR.w));
        }
        __syncthreads();
    }

    #pragma unroll
    for (int mf = 0; mf < 2; mf++) {
        int r0 = wm + mf * 16 + gid;
        int r1 = r0 + 8;
        #pragma unroll
        for (int nf = 0; nf < 4; nf++) {
            int col = n0 + wn + nf * 8 + 2 * p;
            if (m0 + r0 < cnt)
                *(float2*)(g_down + (size_t)(base + r0) * HDIM + col)
                    = make_float2(acc[mf][nf][0], acc[mf][nf][1]);
            if (m0 + r1 < cnt)
                *(float2*)(g_down + (size_t)(base + r1) * HDIM + col)
                    = make_float2(acc[mf][nf][2], acc[mf][nf][3]);
        }
    }
}

// ---------------- kernel 5: weighted combine over top-4 ----------------
__global__ void combine_kernel(float* __restrict__ out) {
    int t = blockIdx.x;
    int h = threadIdx.x * 4;
    float4 acc = make_float4(0.f, 0.f, 0.f, 0.f);
    #pragma unroll
    for (int k = 0; k < TOPK; k++) {
        int   e = g_sel_e[t * TOPK + k];
        int   a = g_off[e] + g_sel_slot[t * TOPK + k];
        float w = g_sel_w[t * TOPK + k];
        float4 v = *(const float4*)(g_down + (size_t)a * HDIM + h);
        acc.x += w * v.x; acc.y += w * v.y;
        acc.z += w * v.z; acc.w += w * v.w;
    }
    *(float4*)(out + (size_t)t * HDIM + h) = acc;
}

// ---------------- launch ----------------
extern "C" void kernel_launch(void* const* d_in, const int* in_sizes, int n_in,
                              void* d_out, int out_size) {
    const float* x   = (const float*)d_in[0];
    const float* wgt = (const float*)d_in[1];
    const float* wgp = (const float*)d_in[2];
    const float* wup = (const float*)d_in[3];
    const float* wdp = (const float*)d_in[4];
    float* out = (float*)d_out;

    int write_logits = (out_size >= T_TOK * HDIM + T_TOK * NEXP) ? 1 : 0;
    float* logits_out = out + (size_t)T_TOK * HDIM;

    zero_kernel<<<1, 32>>>();
    router_kernel<<<T_TOK / 16, 256>>>(x, wgt, logits_out, write_logits);
    scan_kernel<<<1, 32>>>();
    moe_gemm1<<<dim3(IDIM / 64, T_TOK / 128, NEXP), 256>>>(x, wgp, wup);
    moe_gemm2<<<dim3(HDIM / 64, T_TOK / 128, NEXP), 256>>>(wdp);
    combine_kernel<<<T_TOK, HDIM / 4>>>(out);
}